// round 12
// baseline (speedup 1.0000x reference)
#include <cuda_runtime.h>

#define NN   16384
#define EE   524288
#define GG   64
#define HID  128
#define NG   51
#define NL   6

// ---------------- scratch (device globals; no allocation allowed) ----------
__device__ float g_h   [(size_t)NN * HID];
__device__ float g_h2  [(size_t)NN * HID];
__device__ float g_xh  [(size_t)NN * HID];
__device__ float g_agg [(size_t)NN * HID];
__device__ float g_attrT[(size_t)NG * EE];
__device__ float g_C   [EE];
__device__ float g_cnt [GG];

// ---------------- helpers --------------------------------------------------
__device__ __forceinline__ float ssp_f(float x) {
    float sp = (x > 15.f) ? x : __logf(1.f + __expf(x));
    return sp - 0.69314718055994531f;
}

__device__ __forceinline__ void red_add_v4(float* addr, float4 v) {
    asm volatile("red.global.add.v4.f32 [%0], {%1,%2,%3,%4};"
                 :: "l"(addr), "f"(v.x), "f"(v.y), "f"(v.z), "f"(v.w)
                 : "memory");
}

// ---- packed f32x2 primitives ----
__device__ __forceinline__ unsigned long long dup2(float a) {
    unsigned long long r;
    asm("mov.b64 %0, {%1, %1};" : "=l"(r) : "f"(a));
    return r;
}
__device__ __forceinline__ void ffma2(unsigned long long& acc,
                                      unsigned long long a, unsigned long long b) {
    asm("fma.rn.f32x2 %0, %1, %2, %0;" : "+l"(acc) : "l"(a), "l"(b));
}
__device__ __forceinline__ unsigned long long mul2(unsigned long long a,
                                                   unsigned long long b) {
    unsigned long long r;
    asm("mul.rn.f32x2 %0, %1, %2;" : "=l"(r) : "l"(a), "l"(b));
    return r;
}
__device__ __forceinline__ float2 unpack2(unsigned long long v) {
    float2 r;
    asm("mov.b64 {%0, %1}, %2;" : "=f"(r.x), "=f"(r.y) : "l"(v));
    return r;
}

#define FFMA2_BLOCK44(acc2, av, bq)                                       \
    _Pragma("unroll")                                                     \
    for (int _i = 0; _i < 4; _i++) {                                      \
        unsigned long long _ad = dup2((av)[_i]);                          \
        ffma2((acc2)[_i][0], _ad, (bq).x);                                \
        ffma2((acc2)[_i][1], _ad, (bq).y);                                \
    }

// 2-D warp tile mapping: 32 warps = 8 e-blocks x 4 f-blocks.
// Warp covers 16 rows x 32 cols; lane = (le 0..3) x (lf 0..7).
// f0 = wf*32 + lf*4  (warp B footprint = 128B contiguous -> 1 crossbar phase)
// interleaved rows r_i = we*16 + 4i + le (A LDS = 4 consecutive rows -> 1 phase)

// ---------------- setup kernels --------------------------------------------
__global__ void k_init_h(const int* __restrict__ z, const float* __restrict__ emb) {
    int idx = blockIdx.x * 256 + threadIdx.x;
    int n = idx >> 5, q = idx & 31;
    ((float4*)g_h)[idx] = ((const float4*)(emb + (size_t)z[n] * HID))[q];
}

__global__ void k_edge_pre(const float* __restrict__ pos, const int* __restrict__ ei) {
    __shared__ float sA[NG * 128];
    int t = threadIdx.x;
    int eBase = blockIdx.x * 128;
    int e = eBase + t;
    int r = ei[e], c = ei[EE + e];
    float dx = pos[r*3+0] - pos[c*3+0];
    float dy = pos[r*3+1] - pos[c*3+1];
    float dz = pos[r*3+2] - pos[c*3+2];
    float d = sqrtf(dx*dx + dy*dy + dz*dz);
    g_C[e] = 0.5f * (__cosf(d * 0.31415926535897931f) + 1.f);
#pragma unroll
    for (int k = 0; k < NG; k++) {
        float u = d - 0.2f * (float)k;
        sA[k * 128 + t] = __expf(-12.5f * u * u);
    }
    __syncthreads();
    for (int i = t; i < NG * 128; i += 128) {
        int k = i >> 7, q = i & 127;
        g_attrT[(size_t)k * EE + eBase + q] = sA[i];
    }
}

__global__ void k_zero_agg() {
    int idx = blockIdx.x * 256 + threadIdx.x;
    ((float4*)g_agg)[idx] = make_float4(0.f, 0.f, 0.f, 0.f);
}

// ---------------- node GEMM: xh = h @ W (1024 thr, remapped) ----------------
__global__ __launch_bounds__(1024, 1)
void k_gemm_xh(const float* __restrict__ W) {
    extern __shared__ float sm[];
    float* sX = sm;                  // 128*132
    float* sW = sm + 128 * 132;      // 128*128
    int tid = threadIdx.x;
    int rBase = blockIdx.x * 128;

    for (int i = tid; i < 128 * 32; i += 1024) {
        int r = i >> 5, c = i & 31;
        ((float4*)(sX + r * 132))[c] =
            ((const float4*)(g_h + (size_t)(rBase + r) * HID))[c];
    }
    for (int i = tid; i < 128 * 32; i += 1024)
        ((float4*)sW)[i] = ((const float4*)W)[i];
    __syncthreads();

    int warp = tid >> 5, lane = tid & 31;
    int we = warp >> 2, wf = warp & 3;
    int le = lane >> 3, lf = lane & 7;
    int f0 = wf * 32 + lf * 4;
    int r0 = we * 16 + le;                // rows r0 + 4*i
    unsigned long long acc2[4][2];
#pragma unroll
    for (int i = 0; i < 4; i++) { acc2[i][0] = 0ull; acc2[i][1] = 0ull; }

#pragma unroll 1
    for (int k4 = 0; k4 < 128; k4 += 4) {
        float4 av4[4];
#pragma unroll
        for (int i = 0; i < 4; i++)
            av4[i] = *(const float4*)&sX[(r0 + 4*i) * 132 + k4];
#pragma unroll
        for (int kk = 0; kk < 4; kk++) {
            ulonglong2 bq = *(const ulonglong2*)&sW[(k4 + kk) * 128 + f0];
            float av[4];
#pragma unroll
            for (int i = 0; i < 4; i++) av[i] = ((const float*)&av4[i])[kk];
            FFMA2_BLOCK44(acc2, av, bq);
        }
    }
#pragma unroll
    for (int i = 0; i < 4; i++) {
        float2 u0 = unpack2(acc2[i][0]), u1 = unpack2(acc2[i][1]);
        *(float4*)(g_xh + (size_t)(rBase + r0 + 4*i) * HID + f0) =
            make_float4(u0.x, u0.y, u1.x, u1.y);
    }
}

// ---------------- fused edge kernel (1024 thr, remapped) --------------------
__global__ __launch_bounds__(1024, 1)
void k_edge(const int* __restrict__ ei,
            const float* __restrict__ W1, const float* __restrict__ B1,
            const float* __restrict__ W2, const float* __restrict__ B2) {
    extern __shared__ float sm[];
    float* sAT = sm;                       // NG*128
    float* sW1 = sAT + NG * 128;           // NG*128
    float* sW2 = sW1 + NG * 128;           // 128*128
    float* sT  = sW2 + 128 * 128;          // 128*132
    float* sC  = sT  + 128 * 132;          // 128
    int*   sRow = (int*)(sC + 128);        // 128
    int*   sCol = sRow + 128;              // 128

    int tid = threadIdx.x;
    int eBase = blockIdx.x * 128;

    for (int i = tid; i < NG * 32; i += 1024) {
        int k = i >> 5, q = i & 31;
        ((float4*)sAT)[i] = ((const float4*)(g_attrT + (size_t)k * EE + eBase))[q];
    }
    for (int i = tid; i < NG * 32; i += 1024)
        ((float4*)sW1)[i] = ((const float4*)W1)[i];
    for (int i = tid; i < 128 * 32; i += 1024)
        ((float4*)sW2)[i] = ((const float4*)W2)[i];
    if (tid < 128) {
        sC[tid]   = g_C[eBase + tid];
        sRow[tid] = ei[eBase + tid];
        sCol[tid] = ei[EE + eBase + tid];
    }
    __syncthreads();

    int warp = tid >> 5, lane = tid & 31;
    int we = warp >> 2, wf = warp & 3;
    int le = lane >> 3, lf = lane & 7;
    int f0 = wf * 32 + lf * 4;
    int eA = we * 16 + le * 4;            // GEMM1: contiguous rows eA..eA+3
    unsigned long long acc2[4][2];

    // ---- GEMM1: K = 51 (A in [k][e] layout -> vector load of 4 rows) ----
    {
        ulonglong2 bb = *(const ulonglong2*)(B1 + f0);
#pragma unroll
        for (int i = 0; i < 4; i++) { acc2[i][0] = bb.x; acc2[i][1] = bb.y; }
    }
#pragma unroll 3
    for (int k = 0; k < NG; k++) {
        float4 a0 = *(const float4*)&sAT[k * 128 + eA];
        ulonglong2 bq = *(const ulonglong2*)&sW1[k * 128 + f0];
        float av[4] = {a0.x, a0.y, a0.z, a0.w};
        FFMA2_BLOCK44(acc2, av, bq);
    }

    // ssp -> sT rows eA..eA+3
#pragma unroll
    for (int i = 0; i < 4; i++) {
        float2 v0 = unpack2(acc2[i][0]), v1 = unpack2(acc2[i][1]);
        *(float4*)&sT[(eA + i) * 132 + f0] =
            make_float4(ssp_f(v0.x), ssp_f(v0.y), ssp_f(v1.x), ssp_f(v1.y));
    }
    __syncthreads();

    // ---- GEMM2: K = 128 (rows r0 + 4i, interleaved) ----
    int r0 = we * 16 + le;
    {
        ulonglong2 bb = *(const ulonglong2*)(B2 + f0);
#pragma unroll
        for (int i = 0; i < 4; i++) { acc2[i][0] = bb.x; acc2[i][1] = bb.y; }
    }
#pragma unroll 1
    for (int k4 = 0; k4 < 128; k4 += 4) {
        float4 av4[4];
#pragma unroll
        for (int i = 0; i < 4; i++)
            av4[i] = *(const float4*)&sT[(r0 + 4*i) * 132 + k4];
#pragma unroll
        for (int kk = 0; kk < 4; kk++) {
            ulonglong2 bq = *(const ulonglong2*)&sW2[(k4 + kk) * 128 + f0];
            float av[4];
#pragma unroll
            for (int i = 0; i < 4; i++) av[i] = ((const float*)&av4[i])[kk];
            FFMA2_BLOCK44(acc2, av, bq);
        }
    }

    // epilogue: *C, gather xh[col], scatter-add to agg[row]
#pragma unroll
    for (int i = 0; i < 4; i++) {
        int row = r0 + 4*i;
        unsigned long long cd = dup2(sC[row]);
        int cl = sCol[row], rw = sRow[row];
        const float* xr = g_xh + (size_t)cl * HID + f0;
        ulonglong2 xq = *(const ulonglong2*)xr;
        unsigned long long p0 = mul2(mul2(acc2[i][0], cd), xq.x);
        unsigned long long p1 = mul2(mul2(acc2[i][1], cd), xq.y);
        float2 u0 = unpack2(p0), u1 = unpack2(p1);
        red_add_v4(g_agg + (size_t)rw * HID + f0,
                   make_float4(u0.x, u0.y, u1.x, u1.y));
    }
}

// ---------------- fused dual node GEMM (1024 thr, remapped) -----------------
__global__ __launch_bounds__(1024, 1)
void k_dual(const float* __restrict__ X,
            const float* __restrict__ W1, const float* __restrict__ B1,
            const float* __restrict__ W2, const float* __restrict__ B2,
            float* __restrict__ dst, int addMode) {
    extern __shared__ float sm[];
    float* sX  = sm;                  // 128*132
    float* sW1 = sm + 128 * 132;      // 128*128
    float* sW2 = sW1 + 128 * 128;     // 128*128
    int tid = threadIdx.x;
    int rBase = blockIdx.x * 128;

    for (int i = tid; i < 128 * 32; i += 1024) {
        int r = i >> 5, c = i & 31;
        ((float4*)(sX + r * 132))[c] =
            ((const float4*)(X + (size_t)(rBase + r) * HID))[c];
    }
    for (int i = tid; i < 128 * 32; i += 1024)
        ((float4*)sW1)[i] = ((const float4*)W1)[i];
    for (int i = tid; i < 128 * 32; i += 1024)
        ((float4*)sW2)[i] = ((const float4*)W2)[i];
    __syncthreads();

    int warp = tid >> 5, lane = tid & 31;
    int we = warp >> 2, wf = warp & 3;
    int le = lane >> 3, lf = lane & 7;
    int f0 = wf * 32 + lf * 4;
    int r0 = we * 16 + le;                // rows r0 + 4*i
    unsigned long long acc2[4][2];

    // ---- GEMM1 ----
    {
        ulonglong2 bb = *(const ulonglong2*)(B1 + f0);
#pragma unroll
        for (int i = 0; i < 4; i++) { acc2[i][0] = bb.x; acc2[i][1] = bb.y; }
    }
#pragma unroll 1
    for (int k4 = 0; k4 < 128; k4 += 4) {
        float4 av4[4];
#pragma unroll
        for (int i = 0; i < 4; i++)
            av4[i] = *(const float4*)&sX[(r0 + 4*i) * 132 + k4];
#pragma unroll
        for (int kk = 0; kk < 4; kk++) {
            ulonglong2 bq = *(const ulonglong2*)&sW1[(k4 + kk) * 128 + f0];
            float av[4];
#pragma unroll
            for (int i = 0; i < 4; i++) av[i] = ((const float*)&av4[i])[kk];
            FFMA2_BLOCK44(acc2, av, bq);
        }
    }
    __syncthreads();   // everyone done reading sX before it becomes T
#pragma unroll
    for (int i = 0; i < 4; i++) {
        float2 v0 = unpack2(acc2[i][0]), v1 = unpack2(acc2[i][1]);
        *(float4*)&sX[(r0 + 4*i) * 132 + f0] =
            make_float4(ssp_f(v0.x), ssp_f(v0.y), ssp_f(v1.x), ssp_f(v1.y));
    }
    __syncthreads();

    // ---- GEMM2 ----
    {
        ulonglong2 bb = *(const ulonglong2*)(B2 + f0);
#pragma unroll
        for (int i = 0; i < 4; i++) { acc2[i][0] = bb.x; acc2[i][1] = bb.y; }
    }
#pragma unroll 1
    for (int k4 = 0; k4 < 128; k4 += 4) {
        float4 av4[4];
#pragma unroll
        for (int i = 0; i < 4; i++)
            av4[i] = *(const float4*)&sX[(r0 + 4*i) * 132 + k4];
#pragma unroll
        for (int kk = 0; kk < 4; kk++) {
            ulonglong2 bq = *(const ulonglong2*)&sW2[(k4 + kk) * 128 + f0];
            float av[4];
#pragma unroll
            for (int i = 0; i < 4; i++) av[i] = ((const float*)&av4[i])[kk];
            FFMA2_BLOCK44(acc2, av, bq);
        }
    }
#pragma unroll
    for (int i = 0; i < 4; i++) {
        float2 u0 = unpack2(acc2[i][0]), u1 = unpack2(acc2[i][1]);
        float* dp = dst + (size_t)(rBase + r0 + 4*i) * HID + f0;
        if (addMode) {
            float4 d0 = *(float4*)dp;
            d0.x += u0.x; d0.y += u0.y; d0.z += u1.x; d0.w += u1.y;
            *(float4*)dp = d0;
        } else {
            *(float4*)dp = make_float4(u0.x, u0.y, u1.x, u1.y);
        }
    }
}

// ---------------- pooling --------------------------------------------------
__global__ void k_zero_out(float* __restrict__ out) {
    int idx = blockIdx.x * 256 + threadIdx.x;
    if (idx < GG * HID) out[idx] = 0.f;
    if (idx < GG) g_cnt[idx] = 0.f;
}

__global__ void k_pool(const int* __restrict__ batch, float* __restrict__ out) {
    int idx = blockIdx.x * 256 + threadIdx.x;
    int n = idx >> 5, q = idx & 31;
    float4 v = ((const float4*)(g_h2 + (size_t)n * HID))[q];
    int b = batch[n];
    red_add_v4(out + (size_t)b * HID + q * 4, v);
    if (q == 0) atomicAdd(&g_cnt[b], 1.f);
}

__global__ void k_div(float* __restrict__ out) {
    int idx = blockIdx.x * 256 + threadIdx.x;
    if (idx < GG * HID) {
        int g = idx >> 7;
        out[idx] = out[idx] / fmaxf(g_cnt[g], 1.f);
    }
}

// ---------------- host side ------------------------------------------------
extern "C" void kernel_launch(void* const* d_in, const int* in_sizes, int n_in,
                              void* d_out, int out_size) {
    const int*   z       = (const int*)  d_in[0];
    const float* pos     = (const float*)d_in[1];
    const int*   batch   = (const int*)  d_in[2];
    const int*   ei      = (const int*)  d_in[3];
    const float* emb     = (const float*)d_in[4];
    const float* mlp1_w  = (const float*)d_in[5];
    const float* mlp1_b  = (const float*)d_in[6];
    const float* mlp2_w  = (const float*)d_in[7];
    const float* mlp2_b  = (const float*)d_in[8];
    const float* cl1_w   = (const float*)d_in[9];
    const float* cl2_w   = (const float*)d_in[10];
    const float* cl2_b   = (const float*)d_in[11];
    const float* lin_w   = (const float*)d_in[12];
    const float* lin_b   = (const float*)d_in[13];
    const float* out1_w  = (const float*)d_in[14];
    const float* out1_b  = (const float*)d_in[15];
    const float* out2_w  = (const float*)d_in[16];
    const float* out2_b  = (const float*)d_in[17];
    float* out = (float*)d_out;

    float *p_agg, *p_h, *p_h2;
    cudaGetSymbolAddress((void**)&p_agg, g_agg);
    cudaGetSymbolAddress((void**)&p_h,   g_h);
    cudaGetSymbolAddress((void**)&p_h2,  g_h2);

    const int smEdge = (NG*128*2 + 128*128 + 128*132 + 128) * 4 + 256 * 4;
    const int smDual = (128*132 + 2*128*128) * 4;
    const int smG    = (128*132 + 128*128) * 4;
    cudaFuncSetAttribute(k_edge,    cudaFuncAttributeMaxDynamicSharedMemorySize, smEdge);
    cudaFuncSetAttribute(k_dual,    cudaFuncAttributeMaxDynamicSharedMemorySize, smDual);
    cudaFuncSetAttribute(k_gemm_xh, cudaFuncAttributeMaxDynamicSharedMemorySize, smG);

    k_init_h  <<<NN * 32 / 256, 256>>>(z, emb);
    k_edge_pre<<<EE / 128, 128>>>(pos, ei);

    for (int l = 0; l < NL; l++) {
        k_zero_agg<<<NN * HID / 4 / 256, 256>>>();
        k_gemm_xh<<<NN / 128, 1024, smG>>>(cl1_w + (size_t)l * HID * HID);
        k_edge<<<EE / 128, 1024, smEdge>>>(ei,
            mlp1_w + (size_t)l * NG * HID, mlp1_b + (size_t)l * HID,
            mlp2_w + (size_t)l * HID * HID, mlp2_b + (size_t)l * HID);
        k_dual<<<NN / 128, 1024, smDual>>>(p_agg,
            cl2_w + (size_t)l * HID * HID, cl2_b + (size_t)l * HID,
            lin_w + (size_t)l * HID * HID, lin_b + (size_t)l * HID,
            p_h, 1);
    }

    // final output MLP then scatter-mean pooling
    k_dual<<<NN / 128, 1024, smDual>>>(p_h, out1_w, out1_b, out2_w, out2_b, p_h2, 0);
    k_zero_out<<<(GG * HID + 255) / 256, 256>>>(out);
    k_pool<<<NN * 32 / 256, 256>>>(batch, out);
    k_div<<<(GG * HID + 255) / 256, 256>>>(out);
}

// round 14
// speedup vs baseline: 1.9055x; 1.9055x over previous
#include <cuda_runtime.h>
#include <cuda_bf16.h>

#define NN   16384
#define EE   524288
#define GG   64
#define HID  128
#define NG   51
#define NL   6
#define TP   136   // bf16 row stride (128 + 8 pad) for MMA smem tiles

// ---------------- scratch (device globals; no allocation allowed) ----------
__device__ float g_h   [(size_t)NN * HID];
__device__ float g_h2  [(size_t)NN * HID];
__device__ float g_xh  [(size_t)NN * HID];
__device__ float g_agg [(size_t)NN * HID];
__device__ float g_attrT[(size_t)NG * EE];
__device__ float g_C   [EE];
__device__ float g_cnt [GG];

// ---------------- helpers --------------------------------------------------
__device__ __forceinline__ float ssp_f(float x) {
    float sp = (x > 15.f) ? x : __logf(1.f + __expf(x));
    return sp - 0.69314718055994531f;
}

__device__ __forceinline__ void red_add_v4(float* addr, float4 v) {
    asm volatile("red.global.add.v4.f32 [%0], {%1,%2,%3,%4};"
                 :: "l"(addr), "f"(v.x), "f"(v.y), "f"(v.z), "f"(v.w)
                 : "memory");
}
__device__ __forceinline__ void red_add_v2(float* addr, float2 v) {
    asm volatile("red.global.add.v2.f32 [%0], {%1,%2};"
                 :: "l"(addr), "f"(v.x), "f"(v.y)
                 : "memory");
}

// ---- packed f32x2 primitives ----
__device__ __forceinline__ unsigned long long dup2(float a) {
    unsigned long long r;
    asm("mov.b64 %0, {%1, %1};" : "=l"(r) : "f"(a));
    return r;
}
__device__ __forceinline__ void ffma2(unsigned long long& acc,
                                      unsigned long long a, unsigned long long b) {
    asm("fma.rn.f32x2 %0, %1, %2, %0;" : "+l"(acc) : "l"(a), "l"(b));
}
__device__ __forceinline__ float2 unpack2(unsigned long long v) {
    float2 r;
    asm("mov.b64 {%0, %1}, %2;" : "=f"(r.x), "=f"(r.y) : "l"(v));
    return r;
}

#define FFMA2_BLOCK44(acc2, av, bq)                                       \
    _Pragma("unroll")                                                     \
    for (int _i = 0; _i < 4; _i++) {                                      \
        unsigned long long _ad = dup2((av)[_i]);                          \
        ffma2((acc2)[_i][0], _ad, (bq).x);                                \
        ffma2((acc2)[_i][1], _ad, (bq).y);                                \
    }

// bf16 MMA: D(16x8,f32) += A(16x16 row) * B(16x8 col)
__device__ __forceinline__ void mma_bf16(float& d0, float& d1, float& d2, float& d3,
                                         unsigned a0, unsigned a1, unsigned a2, unsigned a3,
                                         unsigned b0, unsigned b1) {
    asm volatile("mma.sync.aligned.m16n8k16.row.col.f32.bf16.bf16.f32 "
                 "{%0,%1,%2,%3}, {%4,%5,%6,%7}, {%8,%9}, {%0,%1,%2,%3};"
                 : "+f"(d0), "+f"(d1), "+f"(d2), "+f"(d3)
                 : "r"(a0), "r"(a1), "r"(a2), "r"(a3), "r"(b0), "r"(b1));
}

// ---------------- setup kernels --------------------------------------------
__global__ void k_init_h(const int* __restrict__ z, const float* __restrict__ emb) {
    int idx = blockIdx.x * 256 + threadIdx.x;
    int n = idx >> 5, q = idx & 31;
    ((float4*)g_h)[idx] = ((const float4*)(emb + (size_t)z[n] * HID))[q];
}

__global__ void k_edge_pre(const float* __restrict__ pos, const int* __restrict__ ei) {
    __shared__ float sA[NG * 128];
    int t = threadIdx.x;
    int eBase = blockIdx.x * 128;
    int e = eBase + t;
    int r = ei[e], c = ei[EE + e];
    float dx = pos[r*3+0] - pos[c*3+0];
    float dy = pos[r*3+1] - pos[c*3+1];
    float dz = pos[r*3+2] - pos[c*3+2];
    float d = sqrtf(dx*dx + dy*dy + dz*dz);
    g_C[e] = 0.5f * (__cosf(d * 0.31415926535897931f) + 1.f);
#pragma unroll
    for (int k = 0; k < NG; k++) {
        float u = d - 0.2f * (float)k;
        sA[k * 128 + t] = __expf(-12.5f * u * u);
    }
    __syncthreads();
    for (int i = t; i < NG * 128; i += 128) {
        int k = i >> 7, q = i & 127;
        g_attrT[(size_t)k * EE + eBase + q] = sA[i];
    }
}

__global__ void k_zero_agg() {
    int idx = blockIdx.x * 256 + threadIdx.x;
    ((float4*)g_agg)[idx] = make_float4(0.f, 0.f, 0.f, 0.f);
}

// ---------------- node GEMM: xh = h @ W (R11 exact) -------------------------
__global__ __launch_bounds__(1024, 1)
void k_gemm_xh(const float* __restrict__ W) {
    extern __shared__ float sm[];
    float* sX = sm;                  // 128*132
    float* sW = sm + 128 * 132;      // 128*128
    int tid = threadIdx.x;
    int rBase = blockIdx.x * 128;

    for (int i = tid; i < 128 * 32; i += 1024) {
        int r = i >> 5, c = i & 31;
        ((float4*)(sX + r * 132))[c] =
            ((const float4*)(g_h + (size_t)(rBase + r) * HID))[c];
    }
    for (int i = tid; i < 128 * 32; i += 1024)
        ((float4*)sW)[i] = ((const float4*)W)[i];
    __syncthreads();

    int tr = tid >> 5, tc = tid & 31, r0 = tr * 4, f0 = tc * 4;
    unsigned long long acc2[4][2];
#pragma unroll
    for (int i = 0; i < 4; i++) { acc2[i][0] = 0ull; acc2[i][1] = 0ull; }

#pragma unroll 1
    for (int k4 = 0; k4 < 128; k4 += 4) {
        float4 av4[4];
#pragma unroll
        for (int i = 0; i < 4; i++)
            av4[i] = *(const float4*)&sX[(r0 + i) * 132 + k4];
#pragma unroll
        for (int kk = 0; kk < 4; kk++) {
            ulonglong2 bq = *(const ulonglong2*)&sW[(k4 + kk) * 128 + f0];
            float av[4];
#pragma unroll
            for (int i = 0; i < 4; i++) av[i] = ((const float*)&av4[i])[kk];
            FFMA2_BLOCK44(acc2, av, bq);
        }
    }
#pragma unroll
    for (int i = 0; i < 4; i++) {
        float2 u0 = unpack2(acc2[i][0]), u1 = unpack2(acc2[i][1]);
        *(float4*)(g_xh + (size_t)(rBase + r0 + i) * HID + f0) =
            make_float4(u0.x, u0.y, u1.x, u1.y);
    }
}

// ---------------- fused edge kernel: fp32 GEMM1 + bf16-split MMA GEMM2 ------
__global__ __launch_bounds__(1024, 1)
void k_edge(const int* __restrict__ ei,
            const float* __restrict__ W1, const float* __restrict__ B1,
            const float* __restrict__ W2, const float* __restrict__ B2) {
    extern __shared__ float sm[];
    float* sAT = sm;                            // NG*128 f32
    float* sW1 = sAT + NG * 128;                // NG*128 f32
    __nv_bfloat16* sThi = (__nv_bfloat16*)(sW1 + NG * 128);  // [e][k] 128*TP
    __nv_bfloat16* sTlo = sThi + 128 * TP;
    __nv_bfloat16* sWhi = sTlo + 128 * TP;      // [n][k] (W2^T) 128*TP
    __nv_bfloat16* sWlo = sWhi + 128 * TP;
    float* sC   = (float*)(sWlo + 128 * TP);    // 128
    int*   sRow = (int*)(sC + 128);
    int*   sCol = sRow + 128;

    int tid = threadIdx.x;
    int eBase = blockIdx.x * 128;

    for (int i = tid; i < NG * 32; i += 1024) {
        int k = i >> 5, q = i & 31;
        ((float4*)sAT)[i] = ((const float4*)(g_attrT + (size_t)k * EE + eBase))[q];
    }
    for (int i = tid; i < NG * 32; i += 1024)
        ((float4*)sW1)[i] = ((const float4*)W1)[i];
    // W2 [k][f] fp32 -> split hi/lo bf16, transposed to [f][k]
    for (int i = tid; i < 128 * 128; i += 1024) {
        int k = i >> 7, f = i & 127;
        float w = W2[i];
        __nv_bfloat16 hi = __float2bfloat16(w);
        float lo = w - __bfloat162float(hi);
        sWhi[f * TP + k] = hi;
        sWlo[f * TP + k] = __float2bfloat16(lo);
    }
    if (tid < 128) {
        sC[tid]   = g_C[eBase + tid];
        sRow[tid] = ei[eBase + tid];
        sCol[tid] = ei[EE + eBase + tid];
    }
    __syncthreads();

    // ---- GEMM1 (fp32 FFMA2, R11 mapping): rows e0..e0+3, cols f0..f0+3 ----
    int tr = tid >> 5, tc = tid & 31, e0 = tr * 4, f0 = tc * 4;
    unsigned long long acc2[4][2];
    {
        ulonglong2 bb = *(const ulonglong2*)(B1 + f0);
#pragma unroll
        for (int i = 0; i < 4; i++) { acc2[i][0] = bb.x; acc2[i][1] = bb.y; }
    }
#pragma unroll 3
    for (int k = 0; k < NG; k++) {
        float4 a0 = *(const float4*)&sAT[k * 128 + e0];
        ulonglong2 bq = *(const ulonglong2*)&sW1[k * 128 + f0];
        float av[4] = {a0.x, a0.y, a0.z, a0.w};
        FFMA2_BLOCK44(acc2, av, bq);
    }

    // ssp -> bf16 hi/lo split into sThi/sTlo
#pragma unroll
    for (int i = 0; i < 4; i++) {
        float2 v0 = unpack2(acc2[i][0]), v1 = unpack2(acc2[i][1]);
        float t0 = ssp_f(v0.x), t1 = ssp_f(v0.y);
        float t2 = ssp_f(v1.x), t3 = ssp_f(v1.y);
        __nv_bfloat162 h01, h23, l01, l23;
        h01.x = __float2bfloat16(t0); h01.y = __float2bfloat16(t1);
        h23.x = __float2bfloat16(t2); h23.y = __float2bfloat16(t3);
        l01.x = __float2bfloat16(t0 - __bfloat162float(h01.x));
        l01.y = __float2bfloat16(t1 - __bfloat162float(h01.y));
        l23.x = __float2bfloat16(t2 - __bfloat162float(h23.x));
        l23.y = __float2bfloat16(t3 - __bfloat162float(h23.y));
        *(__nv_bfloat162*)&sThi[(e0 + i) * TP + f0]     = h01;
        *(__nv_bfloat162*)&sThi[(e0 + i) * TP + f0 + 2] = h23;
        *(__nv_bfloat162*)&sTlo[(e0 + i) * TP + f0]     = l01;
        *(__nv_bfloat162*)&sTlo[(e0 + i) * TP + f0 + 2] = l23;
    }
    __syncthreads();

    // ---- GEMM2: bf16-split tensor-core MMA ----
    // warp tile: 16 rows (we) x 32 cols (wf); 4 m16n8 output tiles per warp
    int warp = tid >> 5, lane = tid & 31;
    int we = warp >> 2, wf = warp & 3;
    int g = lane >> 2, ctg = lane & 3;
    int rA = we * 16 + g;

    float d[4][4];
#pragma unroll
    for (int t = 0; t < 4; t++)
#pragma unroll
        for (int j = 0; j < 4; j++) d[t][j] = 0.f;

#pragma unroll 1
    for (int ks = 0; ks < 8; ks++) {
        int k0 = ks * 16 + ctg * 2;
        unsigned ah0 = *(const unsigned*)&sThi[rA * TP + k0];
        unsigned ah1 = *(const unsigned*)&sThi[(rA + 8) * TP + k0];
        unsigned ah2 = *(const unsigned*)&sThi[rA * TP + k0 + 8];
        unsigned ah3 = *(const unsigned*)&sThi[(rA + 8) * TP + k0 + 8];
        unsigned al0 = *(const unsigned*)&sTlo[rA * TP + k0];
        unsigned al1 = *(const unsigned*)&sTlo[(rA + 8) * TP + k0];
        unsigned al2 = *(const unsigned*)&sTlo[rA * TP + k0 + 8];
        unsigned al3 = *(const unsigned*)&sTlo[(rA + 8) * TP + k0 + 8];
#pragma unroll
        for (int t = 0; t < 4; t++) {
            int nb = wf * 32 + t * 8 + g;
            unsigned bh0 = *(const unsigned*)&sWhi[nb * TP + k0];
            unsigned bh1 = *(const unsigned*)&sWhi[nb * TP + k0 + 8];
            unsigned bl0 = *(const unsigned*)&sWlo[nb * TP + k0];
            unsigned bl1 = *(const unsigned*)&sWlo[nb * TP + k0 + 8];
            mma_bf16(d[t][0], d[t][1], d[t][2], d[t][3],
                     ah0, ah1, ah2, ah3, bh0, bh1);
            mma_bf16(d[t][0], d[t][1], d[t][2], d[t][3],
                     ah0, ah1, ah2, ah3, bl0, bl1);
            mma_bf16(d[t][0], d[t][1], d[t][2], d[t][3],
                     al0, al1, al2, al3, bh0, bh1);
        }
    }

    // epilogue: +bias, *C, gather xh[col], scatter-add to agg[row]
#pragma unroll
    for (int rr = 0; rr < 2; rr++) {
        int row = rA + 8 * rr;
        float Cv = sC[row];
        int cl = sCol[row], rw = sRow[row];
        const float* xr = g_xh + (size_t)cl * HID;
        float* ar = g_agg + (size_t)rw * HID;
#pragma unroll
        for (int t = 0; t < 4; t++) {
            int c0 = wf * 32 + t * 8 + ctg * 2;
            float2 bias = *(const float2*)(B2 + c0);
            float2 xq = __ldg((const float2*)(xr + c0));
            float vx = (d[t][2*rr]     + bias.x) * Cv * xq.x;
            float vy = (d[t][2*rr + 1] + bias.y) * Cv * xq.y;
            red_add_v2(ar + c0, make_float2(vx, vy));
        }
    }
}

// ---------------- fused dual node GEMM (R11 exact) --------------------------
__global__ __launch_bounds__(1024, 1)
void k_dual(const float* __restrict__ X,
            const float* __restrict__ W1, const float* __restrict__ B1,
            const float* __restrict__ W2, const float* __restrict__ B2,
            float* __restrict__ dst, int addMode) {
    extern __shared__ float sm[];
    float* sX  = sm;                  // 128*132
    float* sW1 = sm + 128 * 132;      // 128*128
    float* sW2 = sW1 + 128 * 128;     // 128*128
    int tid = threadIdx.x;
    int rBase = blockIdx.x * 128;

    for (int i = tid; i < 128 * 32; i += 1024) {
        int r = i >> 5, c = i & 31;
        ((float4*)(sX + r * 132))[c] =
            ((const float4*)(X + (size_t)(rBase + r) * HID))[c];
    }
    for (int i = tid; i < 128 * 32; i += 1024)
        ((float4*)sW1)[i] = ((const float4*)W1)[i];
    for (int i = tid; i < 128 * 32; i += 1024)
        ((float4*)sW2)[i] = ((const float4*)W2)[i];
    __syncthreads();

    int tr = tid >> 5, tc = tid & 31, r0 = tr * 4, f0 = tc * 4;
    unsigned long long acc2[4][2];

    {
        ulonglong2 bb = *(const ulonglong2*)(B1 + f0);
#pragma unroll
        for (int i = 0; i < 4; i++) { acc2[i][0] = bb.x; acc2[i][1] = bb.y; }
    }
#pragma unroll 1
    for (int k4 = 0; k4 < 128; k4 += 4) {
        float4 av4[4];
#pragma unroll
        for (int i = 0; i < 4; i++)
            av4[i] = *(const float4*)&sX[(r0 + i) * 132 + k4];
#pragma unroll
        for (int kk = 0; kk < 4; kk++) {
            ulonglong2 bq = *(const ulonglong2*)&sW1[(k4 + kk) * 128 + f0];
            float av[4];
#pragma unroll
            for (int i = 0; i < 4; i++) av[i] = ((const float*)&av4[i])[kk];
            FFMA2_BLOCK44(acc2, av, bq);
        }
    }
    __syncthreads();
#pragma unroll
    for (int i = 0; i < 4; i++) {
        float2 v0 = unpack2(acc2[i][0]), v1 = unpack2(acc2[i][1]);
        *(float4*)&sX[(r0 + i) * 132 + f0] =
            make_float4(ssp_f(v0.x), ssp_f(v0.y), ssp_f(v1.x), ssp_f(v1.y));
    }
    __syncthreads();

    {
        ulonglong2 bb = *(const ulonglong2*)(B2 + f0);
#pragma unroll
        for (int i = 0; i < 4; i++) { acc2[i][0] = bb.x; acc2[i][1] = bb.y; }
    }
#pragma unroll 1
    for (int k4 = 0; k4 < 128; k4 += 4) {
        float4 av4[4];
#pragma unroll
        for (int i = 0; i < 4; i++)
            av4[i] = *(const float4*)&sX[(r0 + i) * 132 + k4];
#pragma unroll
        for (int kk = 0; kk < 4; kk++) {
            ulonglong2 bq = *(const ulonglong2*)&sW2[(k4 + kk) * 128 + f0];
            float av[4];
#pragma unroll
            for (int i = 0; i < 4; i++) av[i] = ((const float*)&av4[i])[kk];
            FFMA2_BLOCK44(acc2, av, bq);
        }
    }
#pragma unroll
    for (int i = 0; i < 4; i++) {
        float2 u0 = unpack2(acc2[i][0]), u1 = unpack2(acc2[i][1]);
        float* dp = dst + (size_t)(rBase + r0 + i) * HID + f0;
        if (addMode) {
            float4 d0 = *(float4*)dp;
            d0.x += u0.x; d0.y += u0.y; d0.z += u1.x; d0.w += u1.y;
            *(float4*)dp = d0;
        } else {
            *(float4*)dp = make_float4(u0.x, u0.y, u1.x, u1.y);
        }
    }
}

// ---------------- pooling --------------------------------------------------
__global__ void k_zero_out(float* __restrict__ out) {
    int idx = blockIdx.x * 256 + threadIdx.x;
    if (idx < GG * HID) out[idx] = 0.f;
    if (idx < GG) g_cnt[idx] = 0.f;
}

__global__ void k_pool(const int* __restrict__ batch, float* __restrict__ out) {
    int idx = blockIdx.x * 256 + threadIdx.x;
    int n = idx >> 5, q = idx & 31;
    float4 v = ((const float4*)(g_h2 + (size_t)n * HID))[q];
    int b = batch[n];
    red_add_v4(out + (size_t)b * HID + q * 4, v);
    if (q == 0) atomicAdd(&g_cnt[b], 1.f);
}

__global__ void k_div(float* __restrict__ out) {
    int idx = blockIdx.x * 256 + threadIdx.x;
    if (idx < GG * HID) {
        int g = idx >> 7;
        out[idx] = out[idx] / fmaxf(g_cnt[g], 1.f);
    }
}

// ---------------- host side ------------------------------------------------
extern "C" void kernel_launch(void* const* d_in, const int* in_sizes, int n_in,
                              void* d_out, int out_size) {
    const int*   z       = (const int*)  d_in[0];
    const float* pos     = (const float*)d_in[1];
    const int*   batch   = (const int*)  d_in[2];
    const int*   ei      = (const int*)  d_in[3];
    const float* emb     = (const float*)d_in[4];
    const float* mlp1_w  = (const float*)d_in[5];
    const float* mlp1_b  = (const float*)d_in[6];
    const float* mlp2_w  = (const float*)d_in[7];
    const float* mlp2_b  = (const float*)d_in[8];
    const float* cl1_w   = (const float*)d_in[9];
    const float* cl2_w   = (const float*)d_in[10];
    const float* cl2_b   = (const float*)d_in[11];
    const float* lin_w   = (const float*)d_in[12];
    const float* lin_b   = (const float*)d_in[13];
    const float* out1_w  = (const float*)d_in[14];
    const float* out1_b  = (const float*)d_in[15];
    const float* out2_w  = (const float*)d_in[16];
    const float* out2_b  = (const float*)d_in[17];
    float* out = (float*)d_out;

    float *p_agg, *p_h, *p_h2;
    cudaGetSymbolAddress((void**)&p_agg, g_agg);
    cudaGetSymbolAddress((void**)&p_h,   g_h);
    cudaGetSymbolAddress((void**)&p_h2,  g_h2);

    // edge smem: sAT+sW1 (fp32) + 4 bf16 tiles + C/Row/Col
    const int smEdge = (NG*128*2) * 4 + 4 * (128*TP) * 2 + 128 * 4 * 3;
    const int smDual = (128*132 + 2*128*128) * 4;
    const int smG    = (128*132 + 128*128) * 4;
    cudaFuncSetAttribute(k_edge,    cudaFuncAttributeMaxDynamicSharedMemorySize, smEdge);
    cudaFuncSetAttribute(k_dual,    cudaFuncAttributeMaxDynamicSharedMemorySize, smDual);
    cudaFuncSetAttribute(k_gemm_xh, cudaFuncAttributeMaxDynamicSharedMemorySize, smG);

    k_init_h  <<<NN * 32 / 256, 256>>>(z, emb);
    k_edge_pre<<<EE / 128, 128>>>(pos, ei);

    for (int l = 0; l < NL; l++) {
        k_zero_agg<<<NN * HID / 4 / 256, 256>>>();
        k_gemm_xh<<<NN / 128, 1024, smG>>>(cl1_w + (size_t)l * HID * HID);
        k_edge<<<EE / 128, 1024, smEdge>>>(ei,
            mlp1_w + (size_t)l * NG * HID, mlp1_b + (size_t)l * HID,
            mlp2_w + (size_t)l * HID * HID, mlp2_b + (size_t)l * HID);
        k_dual<<<NN / 128, 1024, smDual>>>(p_agg,
            cl2_w + (size_t)l * HID * HID, cl2_b + (size_t)l * HID,
            lin_w + (size_t)l * HID * HID, lin_b + (size_t)l * HID,
            p_h, 1);
    }

    // final output MLP then scatter-mean pooling
    k_dual<<<NN / 128, 1024, smDual>>>(p_h, out1_w, out1_b, out2_w, out2_b, p_h2, 0);
    k_zero_out<<<(GG * HID + 255) / 256, 256>>>(out);
    k_pool<<<NN * 32 / 256, 256>>>(batch, out);
    k_div<<<(GG * HID + 255) / 256, 256>>>(out);
}

// round 16
// speedup vs baseline: 2.7488x; 1.4425x over previous
#include <cuda_runtime.h>
#include <cuda_bf16.h>

#define NN   16384
#define EE   524288
#define GG   64
#define HID  128
#define NG   51
#define NL   6
#define TP   136   // bf16 row stride for K=128 MMA tiles
#define TP1  72    // bf16 row stride for K=64 MMA tiles (edge GEMM1)

// pre-split weight arena offsets (bf16 elements)
#define OW1  0           // 6 x 128x64
#define OW2  49152       // 6 x 128x128
#define OCL1 147456
#define OCL2 245760
#define OLIN 344064
#define OO1  442368
#define OO2  458752
#define WTOT 475136

// ---------------- scratch (device globals; no allocation allowed) ----------
__device__ float g_h   [(size_t)NN * HID];
__device__ float g_h2  [(size_t)NN * HID];
__device__ float g_xh  [(size_t)NN * HID];
__device__ float g_agg [(size_t)NN * HID];
__device__ float g_C   [EE];
__device__ float g_cnt [GG];
__device__ __nv_bfloat16 g_whi[WTOT], g_wlo[WTOT];
__device__ __nv_bfloat16 g_attr_hi[(size_t)EE * 64], g_attr_lo[(size_t)EE * 64];

// ---------------- helpers --------------------------------------------------
__device__ __forceinline__ float ssp_f(float x) {
    float sp = (x > 15.f) ? x : __logf(1.f + __expf(x));
    return sp - 0.69314718055994531f;
}
__device__ __forceinline__ void red_add_v4(float* addr, float4 v) {
    asm volatile("red.global.add.v4.f32 [%0], {%1,%2,%3,%4};"
                 :: "l"(addr), "f"(v.x), "f"(v.y), "f"(v.z), "f"(v.w) : "memory");
}
__device__ __forceinline__ void red_add_v2(float* addr, float2 v) {
    asm volatile("red.global.add.v2.f32 [%0], {%1,%2};"
                 :: "l"(addr), "f"(v.x), "f"(v.y) : "memory");
}
__device__ __forceinline__ void mma_bf16(float& d0, float& d1, float& d2, float& d3,
                                         unsigned a0, unsigned a1, unsigned a2, unsigned a3,
                                         unsigned b0, unsigned b1) {
    asm volatile("mma.sync.aligned.m16n8k16.row.col.f32.bf16.bf16.f32 "
                 "{%0,%1,%2,%3}, {%4,%5,%6,%7}, {%8,%9}, {%0,%1,%2,%3};"
                 : "+f"(d0), "+f"(d1), "+f"(d2), "+f"(d3)
                 : "r"(a0), "r"(a1), "r"(a2), "r"(a3), "r"(b0), "r"(b1));
}
// 3-term split MMA on one (A,B) fragment pair
#define MMA3(d, ah0,ah1,ah2,ah3, al0,al1,al2,al3, bh0,bh1, bl0,bl1)       \
    mma_bf16(d[0],d[1],d[2],d[3], ah0,ah1,ah2,ah3, bh0,bh1);              \
    mma_bf16(d[0],d[1],d[2],d[3], ah0,ah1,ah2,ah3, bl0,bl1);              \
    mma_bf16(d[0],d[1],d[2],d[3], al0,al1,al2,al3, bh0,bh1);

__device__ __forceinline__ __nv_bfloat162 split_hi2(float a, float b) {
    __nv_bfloat162 r; r.x = __float2bfloat16(a); r.y = __float2bfloat16(b); return r;
}
__device__ __forceinline__ __nv_bfloat162 split_lo2(float a, float b, __nv_bfloat162 h) {
    __nv_bfloat162 r;
    r.x = __float2bfloat16(a - __bfloat162float(h.x));
    r.y = __float2bfloat16(b - __bfloat162float(h.y));
    return r;
}

// ---------------- prep: split+transpose all weights ------------------------
__global__ void k_prep(const float* __restrict__ mlp1_w, const float* __restrict__ mlp2_w,
                       const float* __restrict__ cl1_w,  const float* __restrict__ cl2_w,
                       const float* __restrict__ lin_w,  const float* __restrict__ out1_w,
                       const float* __restrict__ out2_w) {
    int b = blockIdx.x;
    const float* src; int K, Kpad, dstOff;
    if (b < 6)       { src = mlp1_w + b * NG * 128;        K = NG;  Kpad = 64;  dstOff = OW1  + b * 8192; }
    else if (b < 12) { src = mlp2_w + (b-6) * 16384;       K = 128; Kpad = 128; dstOff = OW2  + (b-6)  * 16384; }
    else if (b < 18) { src = cl1_w  + (b-12) * 16384;      K = 128; Kpad = 128; dstOff = OCL1 + (b-12) * 16384; }
    else if (b < 24) { src = cl2_w  + (b-18) * 16384;      K = 128; Kpad = 128; dstOff = OCL2 + (b-18) * 16384; }
    else if (b < 30) { src = lin_w  + (b-24) * 16384;      K = 128; Kpad = 128; dstOff = OLIN + (b-24) * 16384; }
    else if (b == 30){ src = out1_w;                       K = 128; Kpad = 128; dstOff = OO1; }
    else             { src = out2_w;                       K = 128; Kpad = 128; dstOff = OO2; }
    for (int i = threadIdx.x; i < 128 * Kpad; i += 256) {
        int f = i / Kpad, k = i - f * Kpad;
        float v = (k < K) ? src[k * 128 + f] : 0.f;
        __nv_bfloat16 hi = __float2bfloat16(v);
        g_whi[dstOff + i] = hi;
        g_wlo[dstOff + i] = __float2bfloat16(v - __bfloat162float(hi));
    }
}

// ---------------- setup kernels --------------------------------------------
__global__ void k_init_h(const int* __restrict__ z, const float* __restrict__ emb) {
    int idx = blockIdx.x * 256 + threadIdx.x;
    int n = idx >> 5, q = idx & 31;
    ((float4*)g_h)[idx] = ((const float4*)(emb + (size_t)z[n] * HID))[q];
}

__global__ void k_edge_pre(const float* __restrict__ pos, const int* __restrict__ ei) {
    __shared__ __nv_bfloat16 sGhi[128 * 66], sGlo[128 * 66];
    int t = threadIdx.x;
    int eBase = blockIdx.x * 128;
    int e = eBase + t;
    int r = ei[e], c = ei[EE + e];
    float dx = pos[r*3+0] - pos[c*3+0];
    float dy = pos[r*3+1] - pos[c*3+1];
    float dz = pos[r*3+2] - pos[c*3+2];
    float d = sqrtf(dx*dx + dy*dy + dz*dz);
    g_C[e] = 0.5f * (__cosf(d * 0.31415926535897931f) + 1.f);
#pragma unroll
    for (int k = 0; k < 64; k++) {
        float u = d - 0.2f * (float)k;
        float g = (k < NG) ? __expf(-12.5f * u * u) : 0.f;
        __nv_bfloat16 hi = __float2bfloat16(g);
        sGhi[t * 66 + k] = hi;
        sGlo[t * 66 + k] = __float2bfloat16(g - __bfloat162float(hi));
    }
    __syncthreads();
    for (int i = t; i < 128 * 32; i += 128) {
        int rr = i >> 5, w = i & 31;
        ((unsigned*)(g_attr_hi + (size_t)(eBase + rr) * 64))[w] = *(unsigned*)&sGhi[rr * 66 + w * 2];
        ((unsigned*)(g_attr_lo + (size_t)(eBase + rr) * 64))[w] = *(unsigned*)&sGlo[rr * 66 + w * 2];
    }
}

__global__ void k_zero_agg() {
    int idx = blockIdx.x * 256 + threadIdx.x;
    ((float4*)g_agg)[idx] = make_float4(0.f, 0.f, 0.f, 0.f);
}

// ---------------- node GEMM: xh = h @ W (bf16-split MMA) --------------------
__global__ __launch_bounds__(1024, 1)
void k_gemm_xh(int wOff) {
    extern __shared__ __nv_bfloat16 smb[];
    __nv_bfloat16* sXhi = smb;
    __nv_bfloat16* sXlo = sXhi + 128 * TP;
    __nv_bfloat16* sWhi = sXlo + 128 * TP;
    __nv_bfloat16* sWlo = sWhi + 128 * TP;
    int tid = threadIdx.x;
    int rBase = blockIdx.x * 128;

    for (int i = tid; i < 128 * 32; i += 1024) {
        int r = i >> 5, c4 = i & 31;
        float4 v = ((const float4*)(g_h + (size_t)(rBase + r) * HID))[c4];
        __nv_bfloat162 h01 = split_hi2(v.x, v.y), h23 = split_hi2(v.z, v.w);
        *(__nv_bfloat162*)&sXhi[r * TP + c4*4]     = h01;
        *(__nv_bfloat162*)&sXhi[r * TP + c4*4 + 2] = h23;
        *(__nv_bfloat162*)&sXlo[r * TP + c4*4]     = split_lo2(v.x, v.y, h01);
        *(__nv_bfloat162*)&sXlo[r * TP + c4*4 + 2] = split_lo2(v.z, v.w, h23);
    }
    for (int i = tid; i < 128 * 16; i += 1024) {
        int r = i >> 4, c4 = i & 15;
        *(uint4*)&sWhi[r * TP + c4*8] = ((const uint4*)(g_whi + wOff))[i];
        *(uint4*)&sWlo[r * TP + c4*8] = ((const uint4*)(g_wlo + wOff))[i];
    }
    __syncthreads();

    int warp = tid >> 5, lane = tid & 31;
    int we = warp >> 2, wf = warp & 3;
    int g = lane >> 2, ctg = lane & 3;
    int rA = we * 16 + g;

    float d[4][4];
#pragma unroll
    for (int t = 0; t < 4; t++)
#pragma unroll
        for (int j = 0; j < 4; j++) d[t][j] = 0.f;

#pragma unroll 1
    for (int ks = 0; ks < 8; ks++) {
        int k0 = ks * 16 + ctg * 2;
        unsigned ah0 = *(const unsigned*)&sXhi[rA * TP + k0];
        unsigned ah1 = *(const unsigned*)&sXhi[(rA+8) * TP + k0];
        unsigned ah2 = *(const unsigned*)&sXhi[rA * TP + k0 + 8];
        unsigned ah3 = *(const unsigned*)&sXhi[(rA+8) * TP + k0 + 8];
        unsigned al0 = *(const unsigned*)&sXlo[rA * TP + k0];
        unsigned al1 = *(const unsigned*)&sXlo[(rA+8) * TP + k0];
        unsigned al2 = *(const unsigned*)&sXlo[rA * TP + k0 + 8];
        unsigned al3 = *(const unsigned*)&sXlo[(rA+8) * TP + k0 + 8];
#pragma unroll
        for (int t = 0; t < 4; t++) {
            int nb = wf * 32 + t * 8 + g;
            unsigned bh0 = *(const unsigned*)&sWhi[nb * TP + k0];
            unsigned bh1 = *(const unsigned*)&sWhi[nb * TP + k0 + 8];
            unsigned bl0 = *(const unsigned*)&sWlo[nb * TP + k0];
            unsigned bl1 = *(const unsigned*)&sWlo[nb * TP + k0 + 8];
            MMA3(d[t], ah0,ah1,ah2,ah3, al0,al1,al2,al3, bh0,bh1, bl0,bl1);
        }
    }
#pragma unroll
    for (int rr = 0; rr < 2; rr++) {
        int row = rA + 8 * rr;
        float* dp = g_xh + (size_t)(rBase + row) * HID;
#pragma unroll
        for (int t = 0; t < 4; t++) {
            int c0 = wf * 32 + t * 8 + ctg * 2;
            *(float2*)(dp + c0) = make_float2(d[t][2*rr], d[t][2*rr + 1]);
        }
    }
}

// ---------------- fused edge kernel: both GEMMs bf16-split MMA --------------
__global__ __launch_bounds__(1024, 1)
void k_edge(const int* __restrict__ ei, int w1Off, const float* __restrict__ B1,
            int w2Off, const float* __restrict__ B2) {
    extern __shared__ __nv_bfloat16 smb[];
    __nv_bfloat16* sAhi  = smb;                    // [e][TP1]
    __nv_bfloat16* sAlo  = sAhi  + 128 * TP1;
    __nv_bfloat16* sW1hi = sAlo  + 128 * TP1;      // [f][TP1]
    __nv_bfloat16* sW1lo = sW1hi + 128 * TP1;
    __nv_bfloat16* sThi  = sW1lo + 128 * TP1;      // [e][TP]
    __nv_bfloat16* sTlo  = sThi  + 128 * TP;
    __nv_bfloat16* sW2hi = sTlo  + 128 * TP;       // [f][TP]
    __nv_bfloat16* sW2lo = sW2hi + 128 * TP;
    float* sC   = (float*)(sW2lo + 128 * TP);
    int*   sRow = (int*)(sC + 128);
    int*   sCol = sRow + 128;

    int tid = threadIdx.x;
    int eBase = blockIdx.x * 128;

    for (int i = tid; i < 128 * 8; i += 1024) {
        int r = i >> 3, c4 = i & 7;
        *(uint4*)&sAhi[r * TP1 + c4*8] = ((const uint4*)(g_attr_hi + (size_t)eBase * 64))[i];
        *(uint4*)&sAlo[r * TP1 + c4*8] = ((const uint4*)(g_attr_lo + (size_t)eBase * 64))[i];
    }
    for (int i = tid; i < 128 * 8; i += 1024) {
        int r = i >> 3, c4 = i & 7;
        *(uint4*)&sW1hi[r * TP1 + c4*8] = ((const uint4*)(g_whi + w1Off))[i];
        *(uint4*)&sW1lo[r * TP1 + c4*8] = ((const uint4*)(g_wlo + w1Off))[i];
    }
    for (int i = tid; i < 128 * 16; i += 1024) {
        int r = i >> 4, c4 = i & 15;
        *(uint4*)&sW2hi[r * TP + c4*8] = ((const uint4*)(g_whi + w2Off))[i];
        *(uint4*)&sW2lo[r * TP + c4*8] = ((const uint4*)(g_wlo + w2Off))[i];
    }
    if (tid < 128) {
        sC[tid]   = g_C[eBase + tid];
        sRow[tid] = ei[eBase + tid];
        sCol[tid] = ei[EE + eBase + tid];
    }
    __syncthreads();

    int warp = tid >> 5, lane = tid & 31;
    int we = warp >> 2, wf = warp & 3;
    int g = lane >> 2, ctg = lane & 3;
    int rA = we * 16 + g;

    float d[4][4];
#pragma unroll
    for (int t = 0; t < 4; t++)
#pragma unroll
        for (int j = 0; j < 4; j++) d[t][j] = 0.f;

    // ---- GEMM1: K = 64 (padded), A=[e][k], B=W1^T [f][k] ----
#pragma unroll 1
    for (int ks = 0; ks < 4; ks++) {
        int k0 = ks * 16 + ctg * 2;
        unsigned ah0 = *(const unsigned*)&sAhi[rA * TP1 + k0];
        unsigned ah1 = *(const unsigned*)&sAhi[(rA+8) * TP1 + k0];
        unsigned ah2 = *(const unsigned*)&sAhi[rA * TP1 + k0 + 8];
        unsigned ah3 = *(const unsigned*)&sAhi[(rA+8) * TP1 + k0 + 8];
        unsigned al0 = *(const unsigned*)&sAlo[rA * TP1 + k0];
        unsigned al1 = *(const unsigned*)&sAlo[(rA+8) * TP1 + k0];
        unsigned al2 = *(const unsigned*)&sAlo[rA * TP1 + k0 + 8];
        unsigned al3 = *(const unsigned*)&sAlo[(rA+8) * TP1 + k0 + 8];
#pragma unroll
        for (int t = 0; t < 4; t++) {
            int nb = wf * 32 + t * 8 + g;
            unsigned bh0 = *(const unsigned*)&sW1hi[nb * TP1 + k0];
            unsigned bh1 = *(const unsigned*)&sW1hi[nb * TP1 + k0 + 8];
            unsigned bl0 = *(const unsigned*)&sW1lo[nb * TP1 + k0];
            unsigned bl1 = *(const unsigned*)&sW1lo[nb * TP1 + k0 + 8];
            MMA3(d[t], ah0,ah1,ah2,ah3, al0,al1,al2,al3, bh0,bh1, bl0,bl1);
        }
    }

    // +bias, ssp, split -> sThi/sTlo
#pragma unroll
    for (int rr = 0; rr < 2; rr++) {
        int row = rA + 8 * rr;
#pragma unroll
        for (int t = 0; t < 4; t++) {
            int c0 = wf * 32 + t * 8 + ctg * 2;
            float2 bv = *(const float2*)(B1 + c0);
            float t0 = ssp_f(d[t][2*rr]     + bv.x);
            float t1 = ssp_f(d[t][2*rr + 1] + bv.y);
            __nv_bfloat162 h = split_hi2(t0, t1);
            *(__nv_bfloat162*)&sThi[row * TP + c0] = h;
            *(__nv_bfloat162*)&sTlo[row * TP + c0] = split_lo2(t0, t1, h);
        }
    }
    __syncthreads();

    // ---- GEMM2: K = 128 ----
#pragma unroll
    for (int t = 0; t < 4; t++)
#pragma unroll
        for (int j = 0; j < 4; j++) d[t][j] = 0.f;
#pragma unroll 1
    for (int ks = 0; ks < 8; ks++) {
        int k0 = ks * 16 + ctg * 2;
        unsigned ah0 = *(const unsigned*)&sThi[rA * TP + k0];
        unsigned ah1 = *(const unsigned*)&sThi[(rA+8) * TP + k0];
        unsigned ah2 = *(const unsigned*)&sThi[rA * TP + k0 + 8];
        unsigned ah3 = *(const unsigned*)&sThi[(rA+8) * TP + k0 + 8];
        unsigned al0 = *(const unsigned*)&sTlo[rA * TP + k0];
        unsigned al1 = *(const unsigned*)&sTlo[(rA+8) * TP + k0];
        unsigned al2 = *(const unsigned*)&sTlo[rA * TP + k0 + 8];
        unsigned al3 = *(const unsigned*)&sTlo[(rA+8) * TP + k0 + 8];
#pragma unroll
        for (int t = 0; t < 4; t++) {
            int nb = wf * 32 + t * 8 + g;
            unsigned bh0 = *(const unsigned*)&sW2hi[nb * TP + k0];
            unsigned bh1 = *(const unsigned*)&sW2hi[nb * TP + k0 + 8];
            unsigned bl0 = *(const unsigned*)&sW2lo[nb * TP + k0];
            unsigned bl1 = *(const unsigned*)&sW2lo[nb * TP + k0 + 8];
            MMA3(d[t], ah0,ah1,ah2,ah3, al0,al1,al2,al3, bh0,bh1, bl0,bl1);
        }
    }

    // epilogue: +bias, *C, gather xh[col], scatter-add to agg[row]
#pragma unroll
    for (int rr = 0; rr < 2; rr++) {
        int row = rA + 8 * rr;
        float Cv = sC[row];
        int cl = sCol[row], rw = sRow[row];
        const float* xr = g_xh + (size_t)cl * HID;
        float* ar = g_agg + (size_t)rw * HID;
#pragma unroll
        for (int t = 0; t < 4; t++) {
            int c0 = wf * 32 + t * 8 + ctg * 2;
            float2 bias = *(const float2*)(B2 + c0);
            float2 xq = __ldg((const float2*)(xr + c0));
            float vx = (d[t][2*rr]     + bias.x) * Cv * xq.x;
            float vy = (d[t][2*rr + 1] + bias.y) * Cv * xq.y;
            red_add_v2(ar + c0, make_float2(vx, vy));
        }
    }
}

// ---------------- fused dual node GEMM (bf16-split MMA) ---------------------
__global__ __launch_bounds__(1024, 1)
void k_dual(const float* __restrict__ X, int w1Off, const float* __restrict__ B1,
            int w2Off, const float* __restrict__ B2,
            float* __restrict__ dst, int addMode) {
    extern __shared__ __nv_bfloat16 smb[];
    __nv_bfloat16* sXhi  = smb;                    // [r][TP], becomes T after GEMM1
    __nv_bfloat16* sXlo  = sXhi  + 128 * TP;
    __nv_bfloat16* sW1hi = sXlo  + 128 * TP;
    __nv_bfloat16* sW1lo = sW1hi + 128 * TP;
    __nv_bfloat16* sW2hi = sW1lo + 128 * TP;
    __nv_bfloat16* sW2lo = sW2hi + 128 * TP;
    int tid = threadIdx.x;
    int rBase = blockIdx.x * 128;

    for (int i = tid; i < 128 * 32; i += 1024) {
        int r = i >> 5, c4 = i & 31;
        float4 v = ((const float4*)(X + (size_t)(rBase + r) * HID))[c4];
        __nv_bfloat162 h01 = split_hi2(v.x, v.y), h23 = split_hi2(v.z, v.w);
        *(__nv_bfloat162*)&sXhi[r * TP + c4*4]     = h01;
        *(__nv_bfloat162*)&sXhi[r * TP + c4*4 + 2] = h23;
        *(__nv_bfloat162*)&sXlo[r * TP + c4*4]     = split_lo2(v.x, v.y, h01);
        *(__nv_bfloat162*)&sXlo[r * TP + c4*4 + 2] = split_lo2(v.z, v.w, h23);
    }
    for (int i = tid; i < 128 * 16; i += 1024) {
        int r = i >> 4, c4 = i & 15;
        *(uint4*)&sW1hi[r * TP + c4*8] = ((const uint4*)(g_whi + w1Off))[i];
        *(uint4*)&sW1lo[r * TP + c4*8] = ((const uint4*)(g_wlo + w1Off))[i];
        *(uint4*)&sW2hi[r * TP + c4*8] = ((const uint4*)(g_whi + w2Off))[i];
        *(uint4*)&sW2lo[r * TP + c4*8] = ((const uint4*)(g_wlo + w2Off))[i];
    }
    __syncthreads();

    int warp = tid >> 5, lane = tid & 31;
    int we = warp >> 2, wf = warp & 3;
    int g = lane >> 2, ctg = lane & 3;
    int rA = we * 16 + g;

    float d[4][4];
#pragma unroll
    for (int t = 0; t < 4; t++)
#pragma unroll
        for (int j = 0; j < 4; j++) d[t][j] = 0.f;

    // ---- GEMM1 ----
#pragma unroll 1
    for (int ks = 0; ks < 8; ks++) {
        int k0 = ks * 16 + ctg * 2;
        unsigned ah0 = *(const unsigned*)&sXhi[rA * TP + k0];
        unsigned ah1 = *(const unsigned*)&sXhi[(rA+8) * TP + k0];
        unsigned ah2 = *(const unsigned*)&sXhi[rA * TP + k0 + 8];
        unsigned ah3 = *(const unsigned*)&sXhi[(rA+8) * TP + k0 + 8];
        unsigned al0 = *(const unsigned*)&sXlo[rA * TP + k0];
        unsigned al1 = *(const unsigned*)&sXlo[(rA+8) * TP + k0];
        unsigned al2 = *(const unsigned*)&sXlo[rA * TP + k0 + 8];
        unsigned al3 = *(const unsigned*)&sXlo[(rA+8) * TP + k0 + 8];
#pragma unroll
        for (int t = 0; t < 4; t++) {
            int nb = wf * 32 + t * 8 + g;
            unsigned bh0 = *(const unsigned*)&sW1hi[nb * TP + k0];
            unsigned bh1 = *(const unsigned*)&sW1hi[nb * TP + k0 + 8];
            unsigned bl0 = *(const unsigned*)&sW1lo[nb * TP + k0];
            unsigned bl1 = *(const unsigned*)&sW1lo[nb * TP + k0 + 8];
            MMA3(d[t], ah0,ah1,ah2,ah3, al0,al1,al2,al3, bh0,bh1, bl0,bl1);
        }
    }
    __syncthreads();   // all warps done reading X before overwrite with T
#pragma unroll
    for (int rr = 0; rr < 2; rr++) {
        int row = rA + 8 * rr;
#pragma unroll
        for (int t = 0; t < 4; t++) {
            int c0 = wf * 32 + t * 8 + ctg * 2;
            float2 bv = *(const float2*)(B1 + c0);
            float t0 = ssp_f(d[t][2*rr]     + bv.x);
            float t1 = ssp_f(d[t][2*rr + 1] + bv.y);
            __nv_bfloat162 h = split_hi2(t0, t1);
            *(__nv_bfloat162*)&sXhi[row * TP + c0] = h;
            *(__nv_bfloat162*)&sXlo[row * TP + c0] = split_lo2(t0, t1, h);
        }
    }
    __syncthreads();

    // ---- GEMM2 ----
#pragma unroll
    for (int t = 0; t < 4; t++)
#pragma unroll
        for (int j = 0; j < 4; j++) d[t][j] = 0.f;
#pragma unroll 1
    for (int ks = 0; ks < 8; ks++) {
        int k0 = ks * 16 + ctg * 2;
        unsigned ah0 = *(const unsigned*)&sXhi[rA * TP + k0];
        unsigned ah1 = *(const unsigned*)&sXhi[(rA+8) * TP + k0];
        unsigned ah2 = *(const unsigned*)&sXhi[rA * TP + k0 + 8];
        unsigned ah3 = *(const unsigned*)&sXhi[(rA+8) * TP + k0 + 8];
        unsigned al0 = *(const unsigned*)&sXlo[rA * TP + k0];
        unsigned al1 = *(const unsigned*)&sXlo[(rA+8) * TP + k0];
        unsigned al2 = *(const unsigned*)&sXlo[rA * TP + k0 + 8];
        unsigned al3 = *(const unsigned*)&sXlo[(rA+8) * TP + k0 + 8];
#pragma unroll
        for (int t = 0; t < 4; t++) {
            int nb = wf * 32 + t * 8 + g;
            unsigned bh0 = *(const unsigned*)&sW2hi[nb * TP + k0];
            unsigned bh1 = *(const unsigned*)&sW2hi[nb * TP + k0 + 8];
            unsigned bl0 = *(const unsigned*)&sW2lo[nb * TP + k0];
            unsigned bl1 = *(const unsigned*)&sW2lo[nb * TP + k0 + 8];
            MMA3(d[t], ah0,ah1,ah2,ah3, al0,al1,al2,al3, bh0,bh1, bl0,bl1);
        }
    }
#pragma unroll
    for (int rr = 0; rr < 2; rr++) {
        int row = rA + 8 * rr;
        float* dp = dst + (size_t)(rBase + row) * HID;
#pragma unroll
        for (int t = 0; t < 4; t++) {
            int c0 = wf * 32 + t * 8 + ctg * 2;
            float2 bv = *(const float2*)(B2 + c0);
            float vx = d[t][2*rr]     + bv.x;
            float vy = d[t][2*rr + 1] + bv.y;
            if (addMode) {
                float2 o = *(float2*)(dp + c0);
                vx += o.x; vy += o.y;
            }
            *(float2*)(dp + c0) = make_float2(vx, vy);
        }
    }
}

// ---------------- pooling --------------------------------------------------
__global__ void k_zero_out(float* __restrict__ out) {
    int idx = blockIdx.x * 256 + threadIdx.x;
    if (idx < GG * HID) out[idx] = 0.f;
    if (idx < GG) g_cnt[idx] = 0.f;
}

__global__ void k_pool(const int* __restrict__ batch, float* __restrict__ out) {
    int idx = blockIdx.x * 256 + threadIdx.x;
    int n = idx >> 5, q = idx & 31;
    float4 v = ((const float4*)(g_h2 + (size_t)n * HID))[q];
    int b = batch[n];
    red_add_v4(out + (size_t)b * HID + q * 4, v);
    if (q == 0) atomicAdd(&g_cnt[b], 1.f);
}

__global__ void k_div(float* __restrict__ out) {
    int idx = blockIdx.x * 256 + threadIdx.x;
    if (idx < GG * HID) {
        int g = idx >> 7;
        out[idx] = out[idx] / fmaxf(g_cnt[g], 1.f);
    }
}

// ---------------- host side ------------------------------------------------
extern "C" void kernel_launch(void* const* d_in, const int* in_sizes, int n_in,
                              void* d_out, int out_size) {
    const int*   z       = (const int*)  d_in[0];
    const float* pos     = (const float*)d_in[1];
    const int*   batch   = (const int*)  d_in[2];
    const int*   ei      = (const int*)  d_in[3];
    const float* emb     = (const float*)d_in[4];
    const float* mlp1_w  = (const float*)d_in[5];
    const float* mlp1_b  = (const float*)d_in[6];
    const float* mlp2_w  = (const float*)d_in[7];
    const float* mlp2_b  = (const float*)d_in[8];
    const float* cl1_w   = (const float*)d_in[9];
    const float* cl2_w   = (const float*)d_in[10];
    const float* cl2_b   = (const float*)d_in[11];
    const float* lin_w   = (const float*)d_in[12];
    const float* lin_b   = (const float*)d_in[13];
    const float* out1_w  = (const float*)d_in[14];
    const float* out1_b  = (const float*)d_in[15];
    const float* out2_w  = (const float*)d_in[16];
    const float* out2_b  = (const float*)d_in[17];
    float* out = (float*)d_out;

    float *p_agg, *p_h, *p_h2;
    cudaGetSymbolAddress((void**)&p_agg, g_agg);
    cudaGetSymbolAddress((void**)&p_h,   g_h);
    cudaGetSymbolAddress((void**)&p_h2,  g_h2);

    const int smEdge = (4 * 128 * TP1 + 4 * 128 * TP) * 2 + 128 * 4 * 3;
    const int smDual = 6 * 128 * TP * 2;
    const int smXH   = 4 * 128 * TP * 2;
    cudaFuncSetAttribute(k_edge,    cudaFuncAttributeMaxDynamicSharedMemorySize, smEdge);
    cudaFuncSetAttribute(k_dual,    cudaFuncAttributeMaxDynamicSharedMemorySize, smDual);
    cudaFuncSetAttribute(k_gemm_xh, cudaFuncAttributeMaxDynamicSharedMemorySize, smXH);

    k_prep    <<<32, 256>>>(mlp1_w, mlp2_w, cl1_w, cl2_w, lin_w, out1_w, out2_w);
    k_init_h  <<<NN * 32 / 256, 256>>>(z, emb);
    k_edge_pre<<<EE / 128, 128>>>(pos, ei);

    for (int l = 0; l < NL; l++) {
        k_zero_agg<<<NN * HID / 4 / 256, 256>>>();
        k_gemm_xh<<<NN / 128, 1024, smXH>>>(OCL1 + l * 16384);
        k_edge<<<EE / 128, 1024, smEdge>>>(ei,
            OW1 + l * 8192, mlp1_b + (size_t)l * HID,
            OW2 + l * 16384, mlp2_b + (size_t)l * HID);
        k_dual<<<NN / 128, 1024, smDual>>>(p_agg,
            OCL2 + l * 16384, cl2_b + (size_t)l * HID,
            OLIN + l * 16384, lin_b + (size_t)l * HID,
            p_h, 1);
    }

    // final output MLP then scatter-mean pooling
    k_dual<<<NN / 128, 1024, smDual>>>(p_h, OO1, out1_b, OO2, out2_b, p_h2, 0);
    k_zero_out<<<(GG * HID + 255) / 256, 256>>>(out);
    k_pool<<<NN * 32 / 256, 256>>>(batch, out);
    k_div<<<(GG * HID + 255) / 256, 256>>>(out);
}